// round 14
// baseline (speedup 1.0000x reference)
#include <cuda_runtime.h>
#include <cuda_fp16.h>

#define DFEAT 64
#define DQ 16               // 16 uint2 (4 halves each) per fp16 row
#define MAX_NODES 50000
#define MAX_EDGES 800000
#define SCAN_T 1024
#define MAX_TILES ((MAX_NODES + SCAN_T - 1) / SCAN_T)
#define NBLK 148
#define NTHR 1024

// ---- scratch (device globals; no allocation allowed) ----
__device__ int   g_deg[MAX_NODES];
__device__ int   g_cnt[MAX_NODES];
__device__ float g_dinv[MAX_NODES];
__device__ int   g_rowptr[MAX_NODES + 1];
__device__ int   g_cursor[MAX_NODES];
__device__ int   g_bsum[MAX_TILES];
__device__ int2  g_edge[MAX_EDGES];             // {col, float_as_int(w)}
__device__ uint2 g_hx0[MAX_NODES * DQ];         // feat in fp16
__device__ uint2 g_hx1[MAX_NODES * DQ];         // hop-1 result in fp16
__device__ uint2 g_hx2[MAX_NODES * DQ];         // hop-2 result in fp16
__device__ unsigned g_barcnt = 0;
__device__ unsigned g_bargen = 0;

// Software grid barrier (all NBLK CTAs resident: grid == SM count, 1 CTA/SM).
// Generation counter only grows (equality-compared), count self-resets, so it
// is safe across CUDA-graph replays.
__device__ __forceinline__ void gbar() {
    __syncthreads();
    if (threadIdx.x == 0) {
        __threadfence();
        unsigned my = *((volatile unsigned*)&g_bargen);
        if (atomicAdd(&g_barcnt, 1u) == gridDim.x - 1) {
            g_barcnt = 0;
            __threadfence();
            atomicAdd(&g_bargen, 1u);
        } else {
            while (*((volatile unsigned*)&g_bargen) == my) { __nanosleep(64); }
        }
    }
    __syncthreads();
}

// All five setup phases in one persistent kernel; replaces 5 launches
// (~5us floor each) with 4 grid barriers (~1-2us each).
__global__ __launch_bounds__(NTHR, 1)
void k_setup(const float* __restrict__ feat, const int* __restrict__ src,
             const int* __restrict__ dst, int n, int E) {
    int tid = blockIdx.x * NTHR + threadIdx.x;
    int nth = gridDim.x * NTHR;
    __shared__ int s[SCAN_T];

    // ---- Phase A: zero counters + convert feat fp32 -> fp16 (independent) ----
    for (int i = tid; i < n; i += nth) { g_deg[i] = 0; g_cnt[i] = 0; }
    int tot = n * DQ;
    for (int i = tid; i < tot; i += nth) {
        float4 f = reinterpret_cast<const float4*>(feat)[i];
        __half2 h0 = __floats2half2_rn(f.x, f.y);
        __half2 h1 = __floats2half2_rn(f.z, f.w);
        uint2 u;
        u.x = *reinterpret_cast<unsigned*>(&h0);
        u.y = *reinterpret_cast<unsigned*>(&h1);
        g_hx0[i] = u;
    }
    gbar();

    // ---- Phase B: degree histograms ----
    for (int e = tid; e < E; e += nth) {
        atomicAdd(&g_deg[src[e]], 1);
        atomicAdd(&g_cnt[dst[e]], 1);
    }
    gbar();

    // ---- Phase C: d^{-1/2} + per-tile scans of g_cnt ----
    for (int i = tid; i < n; i += nth) {
        int d = g_deg[i];
        g_dinv[i] = (d > 0) ? rsqrtf((float)d) : 0.0f;
    }
    int ntiles = (n + SCAN_T - 1) / SCAN_T;
    for (int tile = blockIdx.x; tile < ntiles; tile += gridDim.x) {
        int i = tile * SCAN_T + threadIdx.x;
        int v = (i < n) ? g_cnt[i] : 0;
        s[threadIdx.x] = v;
        __syncthreads();
        for (int off = 1; off < SCAN_T; off <<= 1) {
            int u = (threadIdx.x >= (unsigned)off) ? s[threadIdx.x - off] : 0;
            __syncthreads();
            s[threadIdx.x] += u;
            __syncthreads();
        }
        if (i < n) g_rowptr[i] = s[threadIdx.x] - v;   // exclusive within tile
        if (threadIdx.x == SCAN_T - 1) g_bsum[tile] = s[SCAN_T - 1];
        __syncthreads();
    }
    gbar();

    // ---- Phase D: scan tile sums (parallel, per block) + add offsets ----
    {
        int t = threadIdx.x;
        if (t < 64) s[t] = (t < ntiles) ? g_bsum[t] : 0;
        __syncthreads();
        if (t < 64) {
            for (int off = 1; off < 64; off <<= 1) {
                int u = (t >= off) ? s[t - off] : 0;
                __syncthreads();
                s[t] += u;
                __syncthreads();
            }
        } else {
            for (int off = 1; off < 64; off <<= 1) { __syncthreads(); __syncthreads(); }
        }
        if (blockIdx.x == 0 && t == 0) g_rowptr[n] = s[ntiles - 1];
        for (int tile = blockIdx.x; tile < ntiles; tile += gridDim.x) {
            int pref = (tile > 0) ? s[tile - 1] : 0;
            int i = tile * SCAN_T + t;
            if (i < n) {
                int r = g_rowptr[i] + pref;
                g_rowptr[i] = r;
                g_cursor[i] = r;
            }
        }
    }
    gbar();

    // ---- Phase E: fill CSC edge list ----
    for (int e = tid; e < E; e += nth) {
        int d = dst[e];
        int sv = src[e];
        int pos = atomicAdd(&g_cursor[d], 1);
        g_edge[pos] = make_int2(sv, __float_as_int(g_dinv[sv] * g_dinv[d]));
    }
}

__device__ __forceinline__ void hacc(float4& acc, float w, uint2 raw) {
    __half2 h0 = *reinterpret_cast<__half2*>(&raw.x);
    __half2 h1 = *reinterpret_cast<__half2*>(&raw.y);
    float2 f0 = __half22float2(h0);
    float2 f1 = __half22float2(h1);
    acc.x = fmaf(w, f0.x, acc.x);
    acc.y = fmaf(w, f0.y, acc.y);
    acc.z = fmaf(w, f1.x, acc.z);
    acc.w = fmaf(w, f1.y, acc.w);
}

// One row per HALF-WARP (R11/R13 structure, unchanged — full occupancy).
__global__ void k_spmm(float* __restrict__ h, float theta, int init,
                       int xin_sel, int xout_sel, int n) {
    int row = (blockIdx.x * blockDim.x + threadIdx.x) >> 4;
    int qi  = threadIdx.x & 15;
    if (row >= n) return;

    const uint2* __restrict__ x =
        (xin_sel == 0) ? g_hx0 : ((xin_sel == 1) ? g_hx1 : g_hx2);
    uint2* xout = (xout_sel == 0) ? (uint2*)0 : ((xout_sel == 1) ? g_hx1 : g_hx2);

    int beg = g_rowptr[row];
    int end = g_rowptr[row + 1];

    float4 acc = make_float4(0.f, 0.f, 0.f, 0.f);

    int p = beg;
    for (; p + 4 <= end; p += 4) {
        int2 e0 = g_edge[p],     e1 = g_edge[p + 1];
        int2 e2 = g_edge[p + 2], e3 = g_edge[p + 3];
        uint2 v0 = x[e0.x * DQ + qi];
        uint2 v1 = x[e1.x * DQ + qi];
        uint2 v2 = x[e2.x * DQ + qi];
        uint2 v3 = x[e3.x * DQ + qi];
        hacc(acc, __int_as_float(e0.y), v0);
        hacc(acc, __int_as_float(e1.y), v1);
        hacc(acc, __int_as_float(e2.y), v2);
        hacc(acc, __int_as_float(e3.y), v3);
    }
    for (; p < end; p++) {
        int2 e = g_edge[p];
        uint2 v = x[e.x * DQ + qi];
        hacc(acc, __int_as_float(e.y), v);
    }

    int o = row * DQ + qi;
    if (xout) {
        __half2 h0 = __floats2half2_rn(acc.x, acc.y);
        __half2 h1 = __floats2half2_rn(acc.z, acc.w);
        uint2 u;
        u.x = *reinterpret_cast<unsigned*>(&h0);
        u.y = *reinterpret_cast<unsigned*>(&h1);
        xout[o] = u;
    }
    float4* h4 = reinterpret_cast<float4*>(h);
    if (init) {
        h4[o] = make_float4(theta * acc.x, theta * acc.y,
                            theta * acc.z, theta * acc.w);
    } else {
        float4 c = h4[o];
        c.x = fmaf(theta, acc.x, c.x);
        c.y = fmaf(theta, acc.y, c.y);
        c.z = fmaf(theta, acc.z, c.z);
        c.w = fmaf(theta, acc.w, c.w);
        h4[o] = c;
    }
}

extern "C" void kernel_launch(void* const* d_in, const int* in_sizes, int n_in,
                              void* d_out, int out_size) {
    const float* feat = (const float*)d_in[0];
    const int*   src  = (const int*)d_in[1];
    const int*   dst  = (const int*)d_in[2];
    float*       h    = (float*)d_out;

    int n = in_sizes[0] / DFEAT;   // 50000
    int E = in_sizes[1];           // 800000

    k_setup<<<NBLK, NTHR>>>(feat, src, dst, n, E);

    int tb = 256;
    int gs = (n + 15) / 16;   // one row per half-warp
    // h  = 0.80 * (A @ f)      ; x1 -> g_hx1
    k_spmm<<<gs, tb>>>(h, 0.80f, 1, 0, 1, n);
    // h += 0.15 * (A @ x1)     ; x2 -> g_hx2
    k_spmm<<<gs, tb>>>(h, 0.15f, 0, 1, 2, n);
    // h += 0.05 * (A @ x2)
    k_spmm<<<gs, tb>>>(h, 0.05f, 0, 2, 0, n);
}

// round 15
// speedup vs baseline: 1.0604x; 1.0604x over previous
#include <cuda_runtime.h>
#include <cuda_fp16.h>

#define DFEAT 64
#define DQ 16               // 16 uint2 (4 halves each) per fp16 row
#define MAX_NODES 50000
#define MAX_EDGES 800000
#define SCAN_B 1024
#define MAX_BLK ((MAX_NODES + SCAN_B - 1) / SCAN_B)

// ---- scratch (device globals; no allocation allowed) ----
__device__ int   g_deg[MAX_NODES];
__device__ int   g_cnt[MAX_NODES];
__device__ float g_dinv[MAX_NODES];
__device__ int   g_rowptr[MAX_NODES + 1];
__device__ int   g_cursor[MAX_NODES];
__device__ int   g_bsum[MAX_BLK];
__device__ int2  g_edge[MAX_EDGES];             // {col, float_as_int(w)}
__device__ uint2 g_hx0[MAX_NODES * DQ];         // feat in fp16
__device__ uint2 g_hx1[MAX_NODES * DQ];         // x1 = A@f   (fp16)
__device__ uint2 g_hx2[MAX_NODES * DQ];         // x2 = A@x1  (fp16)

__global__ void k_zero(int n) {
    int i = blockIdx.x * blockDim.x + threadIdx.x;
    if (i < n) { g_deg[i] = 0; g_cnt[i] = 0; }
}

__global__ void k_count(const int* __restrict__ src, const int* __restrict__ dst, int E) {
    int e = blockIdx.x * blockDim.x + threadIdx.x;
    if (e < E) {
        atomicAdd(&g_deg[src[e]], 1);
        atomicAdd(&g_cnt[dst[e]], 1);
    }
}

// Fused: blocks [0,nb): tile scan of g_cnt; [nb,2nb): dinv; [2nb,2nb+ncv): feat->fp16.
__global__ void k_prep(const float* __restrict__ feat, int n, int nb, int ncv) {
    int b = (int)blockIdx.x;
    if (b < nb) {
        __shared__ int s[SCAN_B];
        int t = threadIdx.x;
        int i = b * SCAN_B + t;
        int v = (i < n) ? g_cnt[i] : 0;
        s[t] = v;
        __syncthreads();
        for (int off = 1; off < SCAN_B; off <<= 1) {
            int u = (t >= off) ? s[t - off] : 0;
            __syncthreads();
            s[t] += u;
            __syncthreads();
        }
        if (i < n) g_rowptr[i] = s[t] - v;
        if (t == SCAN_B - 1) g_bsum[b] = s[t];
    } else if (b < 2 * nb) {
        int i = (b - nb) * SCAN_B + threadIdx.x;
        if (i < n) {
            int d = g_deg[i];
            g_dinv[i] = (d > 0) ? rsqrtf((float)d) : 0.0f;
        }
    } else {
        int i = (b - 2 * nb) * SCAN_B + threadIdx.x;
        int tot = n * DQ;
        if (i < tot) {
            float4 f = reinterpret_cast<const float4*>(feat)[i];
            __half2 h0 = __floats2half2_rn(f.x, f.y);
            __half2 h1 = __floats2half2_rn(f.z, f.w);
            uint2 u;
            u.x = *reinterpret_cast<unsigned*>(&h0);
            u.y = *reinterpret_cast<unsigned*>(&h1);
            g_hx0[i] = u;
        }
    }
}

// Scan phases 2+3: parallel tile-sum scan + offset add.
__global__ void k_scan3(int n, int nb) {
    __shared__ int s[64];    // nb <= 49
    int t = threadIdx.x;
    if (t < 64) s[t] = (t < nb) ? g_bsum[t] : 0;
    __syncthreads();
    if (t < 64) {
        for (int off = 1; off < 64; off <<= 1) {
            int u = (t >= off) ? s[t - off] : 0;
            __syncthreads();
            s[t] += u;
            __syncthreads();
        }
    } else {
        for (int off = 1; off < 64; off <<= 1) { __syncthreads(); __syncthreads(); }
    }
    int b = (int)blockIdx.x;
    int pref = (b > 0) ? s[b - 1] : 0;
    if (b == nb - 1 && t == 0) g_rowptr[n] = s[nb - 1];
    int i = b * SCAN_B + t;
    if (i < n) {
        int r = g_rowptr[i] + pref;
        g_rowptr[i] = r;
        g_cursor[i] = r;
    }
}

__global__ void k_fill(const int* __restrict__ src, const int* __restrict__ dst, int E) {
    int e = blockIdx.x * blockDim.x + threadIdx.x;
    if (e < E) {
        int d = dst[e];
        int s = src[e];
        int pos = atomicAdd(&g_cursor[d], 1);
        g_edge[pos] = make_int2(s, __float_as_int(g_dinv[s] * g_dinv[d]));
    }
}

__device__ __forceinline__ void hacc(float4& acc, float w, uint2 raw) {
    __half2 h0 = *reinterpret_cast<__half2*>(&raw.x);
    __half2 h1 = *reinterpret_cast<__half2*>(&raw.y);
    float2 f0 = __half22float2(h0);
    float2 f1 = __half22float2(h1);
    acc.x = fmaf(w, f0.x, acc.x);
    acc.y = fmaf(w, f0.y, acc.y);
    acc.z = fmaf(w, f1.x, acc.z);
    acc.w = fmaf(w, f1.y, acc.w);
}

// Shared gather loop: acc = (A @ x)[row] slice for this lane.
__device__ __forceinline__ float4 row_gather(const uint2* __restrict__ x,
                                             int row, int qi) {
    int beg = g_rowptr[row];
    int end = g_rowptr[row + 1];
    float4 acc = make_float4(0.f, 0.f, 0.f, 0.f);
    int p = beg;
    for (; p + 4 <= end; p += 4) {
        int2 e0 = g_edge[p],     e1 = g_edge[p + 1];
        int2 e2 = g_edge[p + 2], e3 = g_edge[p + 3];
        uint2 v0 = x[e0.x * DQ + qi];
        uint2 v1 = x[e1.x * DQ + qi];
        uint2 v2 = x[e2.x * DQ + qi];
        uint2 v3 = x[e3.x * DQ + qi];
        hacc(acc, __int_as_float(e0.y), v0);
        hacc(acc, __int_as_float(e1.y), v1);
        hacc(acc, __int_as_float(e2.y), v2);
        hacc(acc, __int_as_float(e3.y), v3);
    }
    for (; p < end; p++) {
        int2 e = g_edge[p];
        uint2 v = x[e.x * DQ + qi];
        hacc(acc, __int_as_float(e.y), v);
    }
    return acc;
}

// Hops 1-2: xout = fp16(A @ xin). No h access at all.
// xin_sel: 0 = g_hx0, 1 = g_hx1 ; xout_sel: 1 = g_hx1, 2 = g_hx2.
__global__ void k_spmm_x(int xin_sel, int xout_sel, int n) {
    int row = (blockIdx.x * blockDim.x + threadIdx.x) >> 4;
    int qi  = threadIdx.x & 15;
    if (row >= n) return;
    const uint2* __restrict__ x = (xin_sel == 0) ? g_hx0 : g_hx1;
    uint2* xout = (xout_sel == 1) ? g_hx1 : g_hx2;

    float4 acc = row_gather(x, row, qi);

    __half2 h0 = __floats2half2_rn(acc.x, acc.y);
    __half2 h1 = __floats2half2_rn(acc.z, acc.w);
    uint2 u;
    u.x = *reinterpret_cast<unsigned*>(&h0);
    u.y = *reinterpret_cast<unsigned*>(&h1);
    xout[row * DQ + qi] = u;
}

// Hop 3 + combine: x3 = A @ x2 (gather), then
// h[row] = 0.8*x1[row] + 0.15*x2[row] + 0.05*x3  — single coalesced h write.
__global__ void k_spmm_final(float* __restrict__ h, int n) {
    int row = (blockIdx.x * blockDim.x + threadIdx.x) >> 4;
    int qi  = threadIdx.x & 15;
    if (row >= n) return;

    float4 x3 = row_gather(g_hx2, row, qi);

    int o = row * DQ + qi;
    uint2 r1 = g_hx1[o];
    uint2 r2 = g_hx2[o];
    float2 a0 = __half22float2(*reinterpret_cast<__half2*>(&r1.x));
    float2 a1 = __half22float2(*reinterpret_cast<__half2*>(&r1.y));
    float2 b0 = __half22float2(*reinterpret_cast<__half2*>(&r2.x));
    float2 b1 = __half22float2(*reinterpret_cast<__half2*>(&r2.y));

    float4 out;
    out.x = fmaf(0.80f, a0.x, fmaf(0.15f, b0.x, 0.05f * x3.x));
    out.y = fmaf(0.80f, a0.y, fmaf(0.15f, b0.y, 0.05f * x3.y));
    out.z = fmaf(0.80f, a1.x, fmaf(0.15f, b1.x, 0.05f * x3.z));
    out.w = fmaf(0.80f, a1.y, fmaf(0.15f, b1.y, 0.05f * x3.w));
    reinterpret_cast<float4*>(h)[o] = out;
}

extern "C" void kernel_launch(void* const* d_in, const int* in_sizes, int n_in,
                              void* d_out, int out_size) {
    const float* feat = (const float*)d_in[0];
    const int*   src  = (const int*)d_in[1];
    const int*   dst  = (const int*)d_in[2];
    float*       h    = (float*)d_out;

    int n = in_sizes[0] / DFEAT;   // 50000
    int E = in_sizes[1];           // 800000

    int tb = 256;
    int gn = (n + tb - 1) / tb;
    int ge = (E + tb - 1) / tb;
    int nb = (n + SCAN_B - 1) / SCAN_B;
    int ncv = (n * DQ + SCAN_B - 1) / SCAN_B;

    k_zero<<<gn, tb>>>(n);
    k_count<<<ge, tb>>>(src, dst, E);
    k_prep<<<2 * nb + ncv, SCAN_B>>>(feat, n, nb, ncv);
    k_scan3<<<nb, SCAN_B>>>(n, nb);
    k_fill<<<ge, tb>>>(src, dst, E);

    int gs = (n + 15) / 16;   // one row per half-warp
    k_spmm_x<<<gs, tb>>>(0, 1, n);        // x1 = A @ f
    k_spmm_x<<<gs, tb>>>(1, 2, n);        // x2 = A @ x1
    k_spmm_final<<<gs, tb>>>(h, n);       // h = 0.8 x1 + 0.15 x2 + 0.05 (A @ x2)
}

// round 16
// speedup vs baseline: 1.0874x; 1.0254x over previous
#include <cuda_runtime.h>
#include <cuda_fp16.h>

#define DFEAT 64
#define DQ 16               // 16 uint2 per fp16 row (conversion view)
#define DR 8                // 8 uint4 per fp16 row (gather view)
#define MAX_NODES 50000
#define MAX_EDGES 800000
#define SCAN_B 1024
#define MAX_BLK ((MAX_NODES + SCAN_B - 1) / SCAN_B)

// ---- scratch (device globals; zero-initialized at module load) ----
__device__ int   g_deg[MAX_NODES];     // invariant: zero at kernel_launch entry
__device__ int   g_cnt[MAX_NODES];     // invariant: zero at kernel_launch entry
__device__ float g_dinv[MAX_NODES];
__device__ int   g_rowptr[MAX_NODES + 1];
__device__ int   g_cursor[MAX_NODES];
__device__ int   g_bsum[MAX_BLK];
__device__ int2  g_edge[MAX_EDGES];             // {col, float_as_int(w)}
__device__ uint4 g_hx0[MAX_NODES * DR];         // feat in fp16
__device__ uint4 g_hx1[MAX_NODES * DR];         // x1 = A@f   (fp16)
__device__ uint4 g_hx2[MAX_NODES * DR];         // x2 = A@x1  (fp16)

__global__ void k_count(const int* __restrict__ src, const int* __restrict__ dst, int E) {
    int e = blockIdx.x * blockDim.x + threadIdx.x;
    if (e < E) {
        atomicAdd(&g_deg[src[e]], 1);
        atomicAdd(&g_cnt[dst[e]], 1);
    }
}

// Fused: blocks [0,nb): tile scan of g_cnt; [nb,2nb): dinv; [2nb,2nb+ncv): feat->fp16.
__global__ void k_prep(const float* __restrict__ feat, int n, int nb, int ncv) {
    int b = (int)blockIdx.x;
    if (b < nb) {
        __shared__ int s[SCAN_B];
        int t = threadIdx.x;
        int i = b * SCAN_B + t;
        int v = (i < n) ? g_cnt[i] : 0;
        s[t] = v;
        __syncthreads();
        for (int off = 1; off < SCAN_B; off <<= 1) {
            int u = (t >= off) ? s[t - off] : 0;
            __syncthreads();
            s[t] += u;
            __syncthreads();
        }
        if (i < n) g_rowptr[i] = s[t] - v;
        if (t == SCAN_B - 1) g_bsum[b] = s[t];
    } else if (b < 2 * nb) {
        int i = (b - nb) * SCAN_B + threadIdx.x;
        if (i < n) {
            int d = g_deg[i];
            g_dinv[i] = (d > 0) ? rsqrtf((float)d) : 0.0f;
        }
    } else {
        int i = (b - 2 * nb) * SCAN_B + threadIdx.x;
        int tot = n * DQ;
        if (i < tot) {
            float4 f = reinterpret_cast<const float4*>(feat)[i];
            __half2 h0 = __floats2half2_rn(f.x, f.y);
            __half2 h1 = __floats2half2_rn(f.z, f.w);
            uint2 u;
            u.x = *reinterpret_cast<unsigned*>(&h0);
            u.y = *reinterpret_cast<unsigned*>(&h1);
            reinterpret_cast<uint2*>(g_hx0)[i] = u;
        }
    }
}

// Scan phases 2+3 + counter re-zero. g_cnt/g_deg are dead after k_prep; zeroing
// them here restores the entry invariant for the next kernel_launch execution
// (first execution relies on static zero-init of __device__ globals).
__global__ void k_scan3(int n, int nb) {
    __shared__ int s[64];    // nb <= 49
    int t = threadIdx.x;
    if (t < 64) s[t] = (t < nb) ? g_bsum[t] : 0;
    __syncthreads();
    if (t < 64) {
        for (int off = 1; off < 64; off <<= 1) {
            int u = (t >= off) ? s[t - off] : 0;
            __syncthreads();
            s[t] += u;
            __syncthreads();
        }
    } else {
        for (int off = 1; off < 64; off <<= 1) { __syncthreads(); __syncthreads(); }
    }
    int b = (int)blockIdx.x;
    int pref = (b > 0) ? s[b - 1] : 0;
    if (b == nb - 1 && t == 0) g_rowptr[n] = s[nb - 1];
    int i = b * SCAN_B + t;
    if (i < n) {
        int r = g_rowptr[i] + pref;
        g_rowptr[i] = r;
        g_cursor[i] = r;
        g_cnt[i] = 0;          // restore invariant for next run
        g_deg[i] = 0;
    }
}

__global__ void k_fill(const int* __restrict__ src, const int* __restrict__ dst, int E) {
    int e = blockIdx.x * blockDim.x + threadIdx.x;
    if (e < E) {
        int d = dst[e];
        int s = src[e];
        int pos = atomicAdd(&g_cursor[d], 1);
        g_edge[pos] = make_int2(s, __float_as_int(g_dinv[s] * g_dinv[d]));
    }
}

// Accumulate 8 fp16 features (one uint4) into two float4 accumulators.
__device__ __forceinline__ void hacc8(float4& aA, float4& aB, float w, uint4 raw) {
    __half2 h0 = *reinterpret_cast<__half2*>(&raw.x);
    __half2 h1 = *reinterpret_cast<__half2*>(&raw.y);
    __half2 h2 = *reinterpret_cast<__half2*>(&raw.z);
    __half2 h3 = *reinterpret_cast<__half2*>(&raw.w);
    float2 f0 = __half22float2(h0);
    float2 f1 = __half22float2(h1);
    float2 f2 = __half22float2(h2);
    float2 f3 = __half22float2(h3);
    aA.x = fmaf(w, f0.x, aA.x); aA.y = fmaf(w, f0.y, aA.y);
    aA.z = fmaf(w, f1.x, aA.z); aA.w = fmaf(w, f1.y, aA.w);
    aB.x = fmaf(w, f2.x, aB.x); aB.y = fmaf(w, f2.y, aB.y);
    aB.z = fmaf(w, f3.x, aB.z); aB.w = fmaf(w, f3.y, aB.w);
}

// Gather loop: one row per 8 LANES. Lane oi loads one uint4 (8 halves = 16B);
// 8 lanes x 16B = full 128B fp16 row per edge. 2x rows-in-flight vs half-warp
// rows, and per-edge meta/gather instruction count halves.
__device__ __forceinline__ void row_gather8(const uint4* __restrict__ x,
                                            int row, int oi,
                                            float4& aA, float4& aB) {
    int beg = g_rowptr[row];
    int end = g_rowptr[row + 1];
    int p = beg;
    for (; p + 4 <= end; p += 4) {
        int2 e0 = g_edge[p],     e1 = g_edge[p + 1];
        int2 e2 = g_edge[p + 2], e3 = g_edge[p + 3];
        uint4 v0 = x[e0.x * DR + oi];
        uint4 v1 = x[e1.x * DR + oi];
        uint4 v2 = x[e2.x * DR + oi];
        uint4 v3 = x[e3.x * DR + oi];
        hacc8(aA, aB, __int_as_float(e0.y), v0);
        hacc8(aA, aB, __int_as_float(e1.y), v1);
        hacc8(aA, aB, __int_as_float(e2.y), v2);
        hacc8(aA, aB, __int_as_float(e3.y), v3);
    }
    for (; p < end; p++) {
        int2 e = g_edge[p];
        uint4 v = x[e.x * DR + oi];
        hacc8(aA, aB, __int_as_float(e.y), v);
    }
}

__device__ __forceinline__ uint4 pack8(const float4& aA, const float4& aB) {
    __half2 h0 = __floats2half2_rn(aA.x, aA.y);
    __half2 h1 = __floats2half2_rn(aA.z, aA.w);
    __half2 h2 = __floats2half2_rn(aB.x, aB.y);
    __half2 h3 = __floats2half2_rn(aB.z, aB.w);
    uint4 u;
    u.x = *reinterpret_cast<unsigned*>(&h0);
    u.y = *reinterpret_cast<unsigned*>(&h1);
    u.z = *reinterpret_cast<unsigned*>(&h2);
    u.w = *reinterpret_cast<unsigned*>(&h3);
    return u;
}

// Hops 1-2: xout = fp16(A @ xin). No h access.
__global__ void k_spmm_x(int xin_sel, int xout_sel, int n) {
    int row = (blockIdx.x * blockDim.x + threadIdx.x) >> 3;
    int oi  = threadIdx.x & 7;
    if (row >= n) return;
    const uint4* __restrict__ x = (xin_sel == 0) ? g_hx0 : g_hx1;
    uint4* xout = (xout_sel == 1) ? g_hx1 : g_hx2;

    float4 aA = make_float4(0.f, 0.f, 0.f, 0.f);
    float4 aB = make_float4(0.f, 0.f, 0.f, 0.f);
    row_gather8(x, row, oi, aA, aB);
    xout[row * DR + oi] = pack8(aA, aB);
}

// Hop 3 + combine: h[row] = 0.8*x1 + 0.15*x2 + 0.05*(A@x2). Single h write.
__global__ void k_spmm_final(float* __restrict__ h, int n) {
    int row = (blockIdx.x * blockDim.x + threadIdx.x) >> 3;
    int oi  = threadIdx.x & 7;
    if (row >= n) return;

    float4 aA = make_float4(0.f, 0.f, 0.f, 0.f);
    float4 aB = make_float4(0.f, 0.f, 0.f, 0.f);
    row_gather8(g_hx2, row, oi, aA, aB);

    int o = row * DR + oi;
    uint4 r1 = g_hx1[o];
    uint4 r2 = g_hx2[o];
    float2 p0 = __half22float2(*reinterpret_cast<__half2*>(&r1.x));
    float2 p1 = __half22float2(*reinterpret_cast<__half2*>(&r1.y));
    float2 p2 = __half22float2(*reinterpret_cast<__half2*>(&r1.z));
    float2 p3 = __half22float2(*reinterpret_cast<__half2*>(&r1.w));
    float2 q0 = __half22float2(*reinterpret_cast<__half2*>(&r2.x));
    float2 q1 = __half22float2(*reinterpret_cast<__half2*>(&r2.y));
    float2 q2 = __half22float2(*reinterpret_cast<__half2*>(&r2.z));
    float2 q3 = __half22float2(*reinterpret_cast<__half2*>(&r2.w));

    float4 oA, oB;
    oA.x = fmaf(0.80f, p0.x, fmaf(0.15f, q0.x, 0.05f * aA.x));
    oA.y = fmaf(0.80f, p0.y, fmaf(0.15f, q0.y, 0.05f * aA.y));
    oA.z = fmaf(0.80f, p1.x, fmaf(0.15f, q1.x, 0.05f * aA.z));
    oA.w = fmaf(0.80f, p1.y, fmaf(0.15f, q1.y, 0.05f * aA.w));
    oB.x = fmaf(0.80f, p2.x, fmaf(0.15f, q2.x, 0.05f * aB.x));
    oB.y = fmaf(0.80f, p2.y, fmaf(0.15f, q2.y, 0.05f * aB.y));
    oB.z = fmaf(0.80f, p3.x, fmaf(0.15f, q3.x, 0.05f * aB.z));
    oB.w = fmaf(0.80f, p3.y, fmaf(0.15f, q3.y, 0.05f * aB.w));

    float4* h4 = reinterpret_cast<float4*>(h);
    h4[2 * o]     = oA;
    h4[2 * o + 1] = oB;
}

extern "C" void kernel_launch(void* const* d_in, const int* in_sizes, int n_in,
                              void* d_out, int out_size) {
    const float* feat = (const float*)d_in[0];
    const int*   src  = (const int*)d_in[1];
    const int*   dst  = (const int*)d_in[2];
    float*       h    = (float*)d_out;

    int n = in_sizes[0] / DFEAT;   // 50000
    int E = in_sizes[1];           // 800000

    int tb = 256;
    int ge = (E + tb - 1) / tb;
    int nb = (n + SCAN_B - 1) / SCAN_B;
    int ncv = (n * DQ + SCAN_B - 1) / SCAN_B;

    k_count<<<ge, tb>>>(src, dst, E);                 // counters pre-zeroed (invariant)
    k_prep<<<2 * nb + ncv, SCAN_B>>>(feat, n, nb, ncv);
    k_scan3<<<nb, SCAN_B>>>(n, nb);                   // also re-zeros counters
    k_fill<<<ge, tb>>>(src, dst, E);

    int gs = (n * 8 + tb - 1) / tb;   // one row per 8 lanes, 32 rows/block
    k_spmm_x<<<gs, tb>>>(0, 1, n);        // x1 = A @ f
    k_spmm_x<<<gs, tb>>>(1, 2, n);        // x2 = A @ x1
    k_spmm_final<<<gs, tb>>>(h, n);       // h = 0.8 x1 + 0.15 x2 + 0.05 (A @ x2)
}